// round 4
// baseline (speedup 1.0000x reference)
#include <cuda_runtime.h>
#include <math.h>

// ---------------- problem constants (fixed by dataset) ----------------
#define NODES 50000
#define NEDGE 600000
#define ETOT  (NEDGE + NODES)   // edges + self loops
#define FIN   256
#define HID   128
#define NCLS  20
#define NEG_SLOPE 0.2f

// ---------------- scratch (static device globals; referenced directly) ----
__device__ __align__(16) float g_h  [(size_t)NODES * HID];  // GEMM outputs
__device__ __align__(16) float g_x2 [(size_t)NODES * HID];  // aggregation outputs
__device__ __align__(16) float g_as [NODES];
__device__ __align__(16) float g_ad [NODES];
__device__ int g_cnt[NODES];
__device__ int g_rowptr[NODES + 1];
__device__ int g_fill[NODES];
__device__ int g_col[ETOT];
__device__ int g_is64;   // 1 if edge_index is int64 in memory, 0 if int32

// ---------------- dtype probe: int64 layout => odd 32-bit words all zero ----
__global__ void probe_dtype_k(const unsigned int* __restrict__ ei32) {
    // single warp; node ids < 50000 so int64 high words are 0
    int lane = threadIdx.x;
    int odd_nonzero = 0;
    for (int i = lane; i < 64; i += 32)
        if (ei32[2 * i + 1] != 0u) odd_nonzero = 1;
    #pragma unroll
    for (int o = 16; o; o >>= 1)
        odd_nonzero |= __shfl_xor_sync(0xffffffffu, odd_nonzero, o);
    if (lane == 0) g_is64 = odd_nonzero ? 0 : 1;
}

__device__ __forceinline__ int load_edge(const void* ei, long long idx) {
    int v;
    if (g_is64) v = (int)((const long long*)ei)[idx];
    else        v = ((const int*)ei)[idx];
    // clamp defensively: bad value -> wrong answer (diagnosable), never a trap
    return (v < 0) ? 0 : (v >= NODES ? NODES - 1 : v);
}

// ---------------- CSR build ----------------
__global__ void zero_cnt_k() {
    int i = blockIdx.x * blockDim.x + threadIdx.x;
    if (i < NODES) g_cnt[i] = 0;
}

__global__ void count_edges_k(const void* __restrict__ ei) {
    int e = blockIdx.x * blockDim.x + threadIdx.x;
    if (e >= ETOT) return;
    int dst = (e < NEDGE) ? load_edge(ei, (long long)NEDGE + e) : (e - NEDGE);
    atomicAdd(&g_cnt[dst], 1);
}

// single-block exclusive scan over NODES counts -> g_rowptr[NODES+1]
__global__ void scan_k() {
    __shared__ int sh[1024];
    __shared__ int carry_s;
    if (threadIdx.x == 0) carry_s = 0;
    __syncthreads();
    for (int base = 0; base < NODES; base += 1024) {
        int i = base + threadIdx.x;
        int v = (i < NODES) ? g_cnt[i] : 0;
        sh[threadIdx.x] = v;
        __syncthreads();
        for (int off = 1; off < 1024; off <<= 1) {
            int t = 0;
            if (threadIdx.x >= off) t = sh[threadIdx.x - off];
            __syncthreads();
            sh[threadIdx.x] += t;
            __syncthreads();
        }
        int incl  = sh[threadIdx.x];
        int carry = carry_s;
        if (i < NODES) g_rowptr[i] = carry + incl - v;   // exclusive
        __syncthreads();
        if (threadIdx.x == 1023) carry_s = carry + incl;
        __syncthreads();
    }
    if (threadIdx.x == 0) g_rowptr[NODES] = carry_s;
}

__global__ void copy_fill_k() {
    int i = blockIdx.x * blockDim.x + threadIdx.x;
    if (i < NODES) g_fill[i] = g_rowptr[i];
}

__global__ void fill_edges_k(const void* __restrict__ ei) {
    int e = blockIdx.x * blockDim.x + threadIdx.x;
    if (e >= ETOT) return;
    int src, dst;
    if (e < NEDGE) {
        src = load_edge(ei, e);
        dst = load_edge(ei, (long long)NEDGE + e);
    } else {
        src = dst = e - NEDGE;
    }
    int p = atomicAdd(&g_fill[dst], 1);
    g_col[p] = src;
}

// ---------------- SGEMM: g_h[M x 128] = A[M x K] @ B[K x 128] (+bias)(relu) ------
// A_EXT: A comes from kernel param; otherwise A = g_x2.
template <bool A_EXT, bool BIAS, bool RELU>
__global__ __launch_bounds__(256, 2)
void sgemm128_k(const float* __restrict__ Ap, const float* __restrict__ B,
                const float* __restrict__ bias, int M, int K) {
    const int BM = 128, BN = 128, BK = 16, TM = 8, TN = 8;
    const float* A = A_EXT ? Ap : (const float*)g_x2;
    float* C = g_h;

    __shared__ float As[BK][BM + 4];
    __shared__ float Bs[BK][BN];

    const int tid = threadIdx.x;               // 256 threads
    const int block_row = blockIdx.x * BM;
    const int tr = (tid / 16) * TM;
    const int tc = (tid % 16) * TN;

    float acc[TM][TN];
    #pragma unroll
    for (int i = 0; i < TM; i++)
        #pragma unroll
        for (int j = 0; j < TN; j++) acc[i][j] = 0.f;

    const int a_row  = tid / 4;        // 0..63
    const int a_col4 = tid % 4;        // float4 index within 16 cols
    const int b_row  = tid / 32;       // 0..7
    const int b_col4 = tid % 32;       // float4 index within 128 cols

    for (int k0 = 0; k0 < K; k0 += BK) {
        // load A tile (128 x 16), transposed into As[col][row]
        #pragma unroll
        for (int half = 0; half < 2; half++) {
            int r = a_row + half * 64;
            int grow = block_row + r;
            float4 v = make_float4(0.f, 0.f, 0.f, 0.f);
            if (grow < M)
                v = *reinterpret_cast<const float4*>(A + (size_t)grow * K + k0 + a_col4 * 4);
            As[a_col4 * 4 + 0][r] = v.x;
            As[a_col4 * 4 + 1][r] = v.y;
            As[a_col4 * 4 + 2][r] = v.z;
            As[a_col4 * 4 + 3][r] = v.w;
        }
        // load B tile (16 x 128)
        #pragma unroll
        for (int half = 0; half < 2; half++) {
            int r = b_row + half * 8;
            float4 v = *reinterpret_cast<const float4*>(B + (size_t)(k0 + r) * BN + b_col4 * 4);
            *reinterpret_cast<float4*>(&Bs[r][b_col4 * 4]) = v;
        }
        __syncthreads();

        #pragma unroll
        for (int k = 0; k < BK; k++) {
            float ra[TM], rb[TN];
            #pragma unroll
            for (int i = 0; i < TM; i++) ra[i] = As[k][tr + i];
            #pragma unroll
            for (int j = 0; j < TN; j++) rb[j] = Bs[k][tc + j];
            #pragma unroll
            for (int i = 0; i < TM; i++)
                #pragma unroll
                for (int j = 0; j < TN; j++)
                    acc[i][j] = fmaf(ra[i], rb[j], acc[i][j]);
        }
        __syncthreads();
    }

    #pragma unroll
    for (int i = 0; i < TM; i++) {
        int grow = block_row + tr + i;
        if (grow >= M) break;
        #pragma unroll
        for (int j = 0; j < TN; j++) {
            float v = acc[i][j];
            if (BIAS) v += bias[tc + j];
            if (RELU) v = v > 0.f ? v : 0.f;
            C[(size_t)grow * BN + tc + j] = v;
        }
    }
}

// ---------------- per-node attention dots on g_h -> g_as / g_ad ----------------
__global__ void node_dots_k(const float* __restrict__ a_src, const float* __restrict__ a_dst) {
    int node = blockIdx.x * (blockDim.x >> 5) + (threadIdx.x >> 5);
    if (node >= NODES) return;
    int lane = threadIdx.x & 31;
    float4 hv = reinterpret_cast<const float4*>(g_h + (size_t)node * HID)[lane];
    float4 s4 = reinterpret_cast<const float4*>(a_src)[lane];
    float4 d4 = reinterpret_cast<const float4*>(a_dst)[lane];
    float s = hv.x * s4.x + hv.y * s4.y + hv.z * s4.z + hv.w * s4.w;
    float d = hv.x * d4.x + hv.y * d4.y + hv.z * d4.z + hv.w * d4.w;
    #pragma unroll
    for (int o = 16; o; o >>= 1) {
        s += __shfl_xor_sync(0xffffffffu, s, o);
        d += __shfl_xor_sync(0xffffffffu, d, o);
    }
    if (lane == 0) { g_as[node] = s; g_ad[node] = d; }
}

// ---------------- GAT aggregation: one warp per destination node ----------------
// reads g_h / g_as / g_ad / g_rowptr / g_col, writes g_x2
template <bool RELU>
__global__ void gat_aggregate_k(const float* __restrict__ bias) {
    int node = blockIdx.x * (blockDim.x >> 5) + (threadIdx.x >> 5);
    if (node >= NODES) return;
    int lane = threadIdx.x & 31;
    int beg = g_rowptr[node], end = g_rowptr[node + 1];
    float adn = g_ad[node];

    // pass 1: segment max (lanes split edges)
    float m = -INFINITY;
    for (int e = beg + lane; e < end; e += 32) {
        float l = g_as[g_col[e]] + adn;
        l = l > 0.f ? l : NEG_SLOPE * l;
        m = fmaxf(m, l);
    }
    #pragma unroll
    for (int o = 16; o; o >>= 1) m = fmaxf(m, __shfl_xor_sync(0xffffffffu, m, o));

    // pass 2: exp-weighted accumulate (all lanes walk same edges; each lane owns 4 cols)
    float4 acc = make_float4(0.f, 0.f, 0.f, 0.f);
    float denom = 0.f;
    for (int e = beg; e < end; e++) {
        int s = g_col[e];
        float l = g_as[s] + adn;             // broadcast load, identical across lanes
        l = l > 0.f ? l : NEG_SLOPE * l;
        float w = __expf(l - m);
        denom += w;
        float4 hv = reinterpret_cast<const float4*>(g_h + (size_t)s * HID)[lane];
        acc.x = fmaf(w, hv.x, acc.x);
        acc.y = fmaf(w, hv.y, acc.y);
        acc.z = fmaf(w, hv.z, acc.z);
        acc.w = fmaf(w, hv.w, acc.w);
    }
    float inv = 1.f / denom;                 // deg >= 1 (self loop) always
    float4 b4 = reinterpret_cast<const float4*>(bias)[lane];
    float4 o4;
    o4.x = acc.x * inv + b4.x;
    o4.y = acc.y * inv + b4.y;
    o4.z = acc.z * inv + b4.z;
    o4.w = acc.w * inv + b4.w;
    if (RELU) {
        o4.x = fmaxf(o4.x, 0.f); o4.y = fmaxf(o4.y, 0.f);
        o4.z = fmaxf(o4.z, 0.f); o4.w = fmaxf(o4.w, 0.f);
    }
    reinterpret_cast<float4*>(g_x2 + (size_t)node * HID)[lane] = o4;
}

// ---------------- final: out = sigmoid(g_h @ Wm2 + bm2), Wm2: [128 x 20] ----------------
__global__ void mlp_out_k(const float* __restrict__ W, const float* __restrict__ b,
                          float* __restrict__ out) {
    __shared__ float Ws[HID * NCLS];
    __shared__ float bs[NCLS];
    for (int i = threadIdx.x; i < HID * NCLS; i += blockDim.x) Ws[i] = W[i];
    if (threadIdx.x < NCLS) bs[threadIdx.x] = b[threadIdx.x];
    __syncthreads();
    int idx = blockIdx.x * blockDim.x + threadIdx.x;
    int row = idx / NCLS, c = idx % NCLS;
    if (row >= NODES) return;
    const float* zr = g_h + (size_t)row * HID;
    float acc = bs[c];
    #pragma unroll 8
    for (int k = 0; k < HID; k++) acc = fmaf(zr[k], Ws[k * NCLS + c], acc);
    out[idx] = 1.f / (1.f + __expf(-acc));
}

// ---------------- launch ----------------
extern "C" void kernel_launch(void* const* d_in, const int* in_sizes, int n_in,
                              void* d_out, int out_size) {
    const float* x    = (const float*)d_in[0];
    const void*  ei   = d_in[1];                 // int32 or int64 — probed on device
    const float* W1   = (const float*)d_in[2];
    const float* as1  = (const float*)d_in[3];
    const float* ad1  = (const float*)d_in[4];
    const float* b1   = (const float*)d_in[5];
    const float* W2   = (const float*)d_in[6];
    const float* as2  = (const float*)d_in[7];
    const float* ad2  = (const float*)d_in[8];
    const float* b2   = (const float*)d_in[9];
    const float* Wm1  = (const float*)d_in[10];
    const float* bm1  = (const float*)d_in[11];
    const float* Wm2  = (const float*)d_in[12];
    const float* bm2  = (const float*)d_in[13];
    float*       out  = (float*)d_out;

    const int gemm_grid  = (NODES + 127) / 128;      // 391
    const int warps_grid = (NODES + 7) / 8;          // 8 warps/block of 256
    const int edge_grid  = (ETOT + 255) / 256;
    const int node_grid  = (NODES + 255) / 256;

    // --- dtype probe + CSR build (dst-sorted) ---
    probe_dtype_k<<<1, 32>>>((const unsigned int*)ei);
    zero_cnt_k<<<node_grid, 256>>>();
    count_edges_k<<<edge_grid, 256>>>(ei);
    scan_k<<<1, 1024>>>();
    copy_fill_k<<<node_grid, 256>>>();
    fill_edges_k<<<edge_grid, 256>>>(ei);

    // --- GAT layer 1 ---
    sgemm128_k<true, false, false><<<gemm_grid, 256>>>(x, W1, nullptr, NODES, FIN);
    node_dots_k<<<warps_grid, 256>>>(as1, ad1);
    gat_aggregate_k<true><<<warps_grid, 256>>>(b1);

    // --- GAT layer 2 ---
    sgemm128_k<false, false, false><<<gemm_grid, 256>>>(nullptr, W2, nullptr, NODES, HID);
    node_dots_k<<<warps_grid, 256>>>(as2, ad2);
    gat_aggregate_k<false><<<warps_grid, 256>>>(b2);

    // --- MLP head ---
    sgemm128_k<false, true, true><<<gemm_grid, 256>>>(nullptr, Wm1, bm1, NODES, HID);
    mlp_out_k<<<(NODES * NCLS + 319) / 320, 320>>>(Wm2, bm2, out);
}

// round 5
// speedup vs baseline: 1.1635x; 1.1635x over previous
#include <cuda_runtime.h>
#include <math.h>
#include <stdint.h>

// ---------------- problem constants (fixed by dataset) ----------------
#define NODES 50000
#define NEDGE 600000
#define ETOT  (NEDGE + NODES)   // edges + self loops
#define FIN   256
#define HID   128
#define NCLS  20
#define NEG_SLOPE 0.2f

#define SCAN_BLK 1024
#define NTILES ((NODES + SCAN_BLK - 1) / SCAN_BLK)   // 49

// ---------------- scratch (static device globals; referenced directly) ----
__device__ __align__(16) float g_h  [(size_t)NODES * HID];  // GEMM outputs
__device__ __align__(16) float g_x2 [(size_t)NODES * HID];  // aggregation outputs
__device__ __align__(16) float g_as [NODES];
__device__ __align__(16) float g_ad [NODES];
__device__ int g_cnt[NODES];
__device__ int g_rowptr[NODES + 1];
__device__ int g_fill[NODES];
__device__ int g_col[ETOT];
__device__ int g_tilesum[NTILES];
__device__ int g_tileoff[NTILES];
__device__ int g_is64;   // 1 if edge_index is int64 in memory, 0 if int32

// ---------------- cp.async helpers ----------------
__device__ __forceinline__ void cp_async16(uint32_t dst, const void* src, int src_bytes) {
    asm volatile("cp.async.cg.shared.global [%0], [%1], 16, %2;"
                 :: "r"(dst), "l"(src), "r"(src_bytes));
}
__device__ __forceinline__ void cp_commit() { asm volatile("cp.async.commit_group;"); }
template <int N>
__device__ __forceinline__ void cp_wait() { asm volatile("cp.async.wait_group %0;" :: "n"(N)); }

// ---------------- dtype probe: int64 layout => odd 32-bit words all zero ----
__global__ void probe_dtype_k(const unsigned int* __restrict__ ei32) {
    int lane = threadIdx.x;
    int odd_nonzero = 0;
    for (int i = lane; i < 64; i += 32)
        if (ei32[2 * i + 1] != 0u) odd_nonzero = 1;
    #pragma unroll
    for (int o = 16; o; o >>= 1)
        odd_nonzero |= __shfl_xor_sync(0xffffffffu, odd_nonzero, o);
    if (lane == 0) g_is64 = odd_nonzero ? 0 : 1;
}

__device__ __forceinline__ int load_edge(const void* ei, long long idx) {
    int v;
    if (g_is64) v = (int)((const long long*)ei)[idx];
    else        v = ((const int*)ei)[idx];
    return (v < 0) ? 0 : (v >= NODES ? NODES - 1 : v);
}

// ---------------- CSR build ----------------
__global__ void zero_cnt_k() {
    int i = blockIdx.x * blockDim.x + threadIdx.x;
    if (i < NODES) g_cnt[i] = 0;
}

__global__ void count_edges_k(const void* __restrict__ ei) {
    int e = blockIdx.x * blockDim.x + threadIdx.x;
    if (e >= ETOT) return;
    int dst = (e < NEDGE) ? load_edge(ei, (long long)NEDGE + e) : (e - NEDGE);
    atomicAdd(&g_cnt[dst], 1);
}

// phase 1: per-block local exclusive scan; write tile sums
__global__ void scan_phase1_k() {
    __shared__ int sh[SCAN_BLK];
    int t = threadIdx.x;
    int i = blockIdx.x * SCAN_BLK + t;
    int v = (i < NODES) ? g_cnt[i] : 0;
    sh[t] = v;
    __syncthreads();
    for (int off = 1; off < SCAN_BLK; off <<= 1) {
        int x = 0;
        if (t >= off) x = sh[t - off];
        __syncthreads();
        sh[t] += x;
        __syncthreads();
    }
    if (i < NODES) g_rowptr[i] = sh[t] - v;          // local exclusive
    if (t == SCAN_BLK - 1) g_tilesum[blockIdx.x] = sh[t];
}

// phase 2: one small block scans the 49 tile sums (exclusive) + total
__global__ void scan_phase2_k() {
    __shared__ int sh[64];
    int t = threadIdx.x;                              // 64 threads
    int v = (t < NTILES) ? g_tilesum[t] : 0;
    sh[t] = v;
    __syncthreads();
    for (int off = 1; off < 64; off <<= 1) {
        int x = 0;
        if (t >= off) x = sh[t - off];
        __syncthreads();
        sh[t] += x;
        __syncthreads();
    }
    if (t < NTILES) g_tileoff[t] = sh[t] - v;
    if (t == 63) g_rowptr[NODES] = sh[63];
}

// phase 3: add tile offsets; init fill cursors
__global__ void scan_phase3_k() {
    int i = blockIdx.x * blockDim.x + threadIdx.x;
    if (i >= NODES) return;
    int r = g_rowptr[i] + g_tileoff[i / SCAN_BLK];
    g_rowptr[i] = r;
    g_fill[i]   = r;
}

__global__ void fill_edges_k(const void* __restrict__ ei) {
    int e = blockIdx.x * blockDim.x + threadIdx.x;
    if (e >= ETOT) return;
    int src, dst;
    if (e < NEDGE) {
        src = load_edge(ei, e);
        dst = load_edge(ei, (long long)NEDGE + e);
    } else {
        src = dst = e - NEDGE;
    }
    int p = atomicAdd(&g_fill[dst], 1);
    g_col[p] = src;
}

// ---------------- SGEMM: g_h[M x 128] = A[M x K] @ B[K x 128] (+bias)(relu) ------
// Double-buffered cp.async pipeline. A_EXT: A from param; otherwise A = g_x2.
template <bool A_EXT, bool BIAS, bool RELU>
__global__ __launch_bounds__(256, 2)
void sgemm128_k(const float* __restrict__ Ap, const float* __restrict__ B,
                const float* __restrict__ bias, int M, int K) {
    const int BM = 128, BN = 128, BK = 16, TM = 8, TN = 8, ASTR = BK + 4; // 20 floats: 16B-aligned rows
    const float* A = A_EXT ? Ap : (const float*)g_x2;
    float* C = g_h;

    __shared__ float As[2][BM][ASTR];   // row-major A tiles
    __shared__ float Bs[2][BK][BN];

    const int tid = threadIdx.x;               // 256 threads
    const int block_row = blockIdx.x * BM;
    const int tr = (tid / 16) * TM;
    const int tc = (tid % 16) * TN;

    const int a_row  = tid / 4;        // 0..63
    const int a_col4 = tid % 4;        // float4 index within 16 cols
    const int b_row  = tid / 32;       // 0..7
    const int b_col4 = tid % 32;       // float4 index within 128 cols

    float acc[TM][TN];
    #pragma unroll
    for (int i = 0; i < TM; i++)
        #pragma unroll
        for (int j = 0; j < TN; j++) acc[i][j] = 0.f;

    auto load_tile = [&](int k0, int s) {
        #pragma unroll
        for (int half = 0; half < 2; half++) {
            int r = a_row + half * 64;
            int grow = block_row + r;
            const float* src = A + (size_t)grow * K + k0 + a_col4 * 4;
            uint32_t dst = (uint32_t)__cvta_generic_to_shared(&As[s][r][a_col4 * 4]);
            cp_async16(dst, src, (grow < M) ? 16 : 0);
        }
        #pragma unroll
        for (int half = 0; half < 2; half++) {
            int r = b_row + half * 8;
            const float* src = B + (size_t)(k0 + r) * BN + b_col4 * 4;
            uint32_t dst = (uint32_t)__cvta_generic_to_shared(&Bs[s][r][b_col4 * 4]);
            cp_async16(dst, src, 16);
        }
    };

    load_tile(0, 0);
    cp_commit();

    int buf = 0;
    for (int k0 = 0; k0 < K; k0 += BK) {
        if (k0 + BK < K) load_tile(k0 + BK, buf ^ 1);
        cp_commit();
        cp_wait<1>();
        __syncthreads();

        #pragma unroll
        for (int k = 0; k < BK; k++) {
            float ra[TM], rb[TN];
            #pragma unroll
            for (int i = 0; i < TM; i++) ra[i] = As[buf][tr + i][k];
            #pragma unroll
            for (int j = 0; j < TN; j++) rb[j] = Bs[buf][k][tc + j];
            #pragma unroll
            for (int i = 0; i < TM; i++)
                #pragma unroll
                for (int j = 0; j < TN; j++)
                    acc[i][j] = fmaf(ra[i], rb[j], acc[i][j]);
        }
        __syncthreads();
        buf ^= 1;
    }
    cp_wait<0>();

    #pragma unroll
    for (int i = 0; i < TM; i++) {
        int grow = block_row + tr + i;
        if (grow >= M) break;
        #pragma unroll
        for (int j = 0; j < TN; j++) {
            float v = acc[i][j];
            if (BIAS) v += bias[tc + j];
            if (RELU) v = v > 0.f ? v : 0.f;
            C[(size_t)grow * BN + tc + j] = v;
        }
    }
}

// ---------------- per-node attention dots on g_h -> g_as / g_ad ----------------
__global__ void node_dots_k(const float* __restrict__ a_src, const float* __restrict__ a_dst) {
    int node = blockIdx.x * (blockDim.x >> 5) + (threadIdx.x >> 5);
    if (node >= NODES) return;
    int lane = threadIdx.x & 31;
    float4 hv = reinterpret_cast<const float4*>(g_h + (size_t)node * HID)[lane];
    float4 s4 = reinterpret_cast<const float4*>(a_src)[lane];
    float4 d4 = reinterpret_cast<const float4*>(a_dst)[lane];
    float s = hv.x * s4.x + hv.y * s4.y + hv.z * s4.z + hv.w * s4.w;
    float d = hv.x * d4.x + hv.y * d4.y + hv.z * d4.z + hv.w * d4.w;
    #pragma unroll
    for (int o = 16; o; o >>= 1) {
        s += __shfl_xor_sync(0xffffffffu, s, o);
        d += __shfl_xor_sync(0xffffffffu, d, o);
    }
    if (lane == 0) { g_as[node] = s; g_ad[node] = d; }
}

// ---------------- GAT aggregation: one warp per destination node ----------------
template <bool RELU>
__global__ void gat_aggregate_k(const float* __restrict__ bias) {
    int node = blockIdx.x * (blockDim.x >> 5) + (threadIdx.x >> 5);
    if (node >= NODES) return;
    int lane = threadIdx.x & 31;
    int beg = g_rowptr[node], end = g_rowptr[node + 1];
    float adn = g_ad[node];

    // pass 1: segment max (lanes split edges)
    float m = -INFINITY;
    for (int e = beg + lane; e < end; e += 32) {
        float l = g_as[g_col[e]] + adn;
        l = l > 0.f ? l : NEG_SLOPE * l;
        m = fmaxf(m, l);
    }
    #pragma unroll
    for (int o = 16; o; o >>= 1) m = fmaxf(m, __shfl_xor_sync(0xffffffffu, m, o));

    // pass 2: exp-weighted accumulate (lanes own 4 columns each)
    float4 acc = make_float4(0.f, 0.f, 0.f, 0.f);
    float denom = 0.f;
    for (int e = beg; e < end; e++) {
        int s = g_col[e];
        float l = g_as[s] + adn;
        l = l > 0.f ? l : NEG_SLOPE * l;
        float w = __expf(l - m);
        denom += w;
        float4 hv = reinterpret_cast<const float4*>(g_h + (size_t)s * HID)[lane];
        acc.x = fmaf(w, hv.x, acc.x);
        acc.y = fmaf(w, hv.y, acc.y);
        acc.z = fmaf(w, hv.z, acc.z);
        acc.w = fmaf(w, hv.w, acc.w);
    }
    float inv = 1.f / denom;
    float4 b4 = reinterpret_cast<const float4*>(bias)[lane];
    float4 o4;
    o4.x = acc.x * inv + b4.x;
    o4.y = acc.y * inv + b4.y;
    o4.z = acc.z * inv + b4.z;
    o4.w = acc.w * inv + b4.w;
    if (RELU) {
        o4.x = fmaxf(o4.x, 0.f); o4.y = fmaxf(o4.y, 0.f);
        o4.z = fmaxf(o4.z, 0.f); o4.w = fmaxf(o4.w, 0.f);
    }
    reinterpret_cast<float4*>(g_x2 + (size_t)node * HID)[lane] = o4;
}

// ---------------- final: out = sigmoid(g_h @ Wm2 + bm2), Wm2: [128 x 20] ----------------
__global__ void mlp_out_k(const float* __restrict__ W, const float* __restrict__ b,
                          float* __restrict__ out) {
    __shared__ float Ws[HID * NCLS];
    __shared__ float bs[NCLS];
    for (int i = threadIdx.x; i < HID * NCLS; i += blockDim.x) Ws[i] = W[i];
    if (threadIdx.x < NCLS) bs[threadIdx.x] = b[threadIdx.x];
    __syncthreads();
    int idx = blockIdx.x * blockDim.x + threadIdx.x;
    int row = idx / NCLS, c = idx % NCLS;
    if (row >= NODES) return;
    const float* zr = g_h + (size_t)row * HID;
    float acc = bs[c];
    #pragma unroll 8
    for (int k = 0; k < HID; k++) acc = fmaf(zr[k], Ws[k * NCLS + c], acc);
    out[idx] = 1.f / (1.f + __expf(-acc));
}

// ---------------- launch ----------------
extern "C" void kernel_launch(void* const* d_in, const int* in_sizes, int n_in,
                              void* d_out, int out_size) {
    const float* x    = (const float*)d_in[0];
    const void*  ei   = d_in[1];                 // int32 or int64 — probed on device
    const float* W1   = (const float*)d_in[2];
    const float* as1  = (const float*)d_in[3];
    const float* ad1  = (const float*)d_in[4];
    const float* b1   = (const float*)d_in[5];
    const float* W2   = (const float*)d_in[6];
    const float* as2  = (const float*)d_in[7];
    const float* ad2  = (const float*)d_in[8];
    const float* b2   = (const float*)d_in[9];
    const float* Wm1  = (const float*)d_in[10];
    const float* bm1  = (const float*)d_in[11];
    const float* Wm2  = (const float*)d_in[12];
    const float* bm2  = (const float*)d_in[13];
    float*       out  = (float*)d_out;

    const int gemm_grid  = (NODES + 127) / 128;      // 391
    const int warps_grid = (NODES + 7) / 8;          // 8 warps/block of 256
    const int edge_grid  = (ETOT + 255) / 256;
    const int node_grid  = (NODES + 255) / 256;

    // --- dtype probe + CSR build (dst-sorted) ---
    probe_dtype_k<<<1, 32>>>((const unsigned int*)ei);
    zero_cnt_k<<<node_grid, 256>>>();
    count_edges_k<<<edge_grid, 256>>>(ei);
    scan_phase1_k<<<NTILES, SCAN_BLK>>>();
    scan_phase2_k<<<1, 64>>>();
    scan_phase3_k<<<node_grid, 256>>>();
    fill_edges_k<<<edge_grid, 256>>>(ei);

    // --- GAT layer 1 ---
    sgemm128_k<true, false, false><<<gemm_grid, 256>>>(x, W1, nullptr, NODES, FIN);
    node_dots_k<<<warps_grid, 256>>>(as1, ad1);
    gat_aggregate_k<true><<<warps_grid, 256>>>(b1);

    // --- GAT layer 2 ---
    sgemm128_k<false, false, false><<<gemm_grid, 256>>>(nullptr, W2, nullptr, NODES, HID);
    node_dots_k<<<warps_grid, 256>>>(as2, ad2);
    gat_aggregate_k<false><<<warps_grid, 256>>>(b2);

    // --- MLP head ---
    sgemm128_k<false, true, true><<<gemm_grid, 256>>>(nullptr, Wm1, bm1, NODES, HID);
    mlp_out_k<<<(NODES * NCLS + 319) / 320, 320>>>(Wm2, bm2, out);
}

// round 6
// speedup vs baseline: 1.8224x; 1.5662x over previous
#include <cuda_runtime.h>
#include <math.h>
#include <stdint.h>

// ---------------- problem constants (fixed by dataset) ----------------
#define NODES 50000
#define NEDGE 600000
#define ETOT  (NEDGE + NODES)   // edges + self loops
#define FIN   256
#define HID   128
#define NCLS  20
#define NEG_SLOPE 0.2f

#define SCAN_BLK 1024
#define NTILES ((NODES + SCAN_BLK - 1) / SCAN_BLK)   // 49

// ---------------- scratch (static device globals; referenced directly) ----
__device__ __align__(16) float g_h  [(size_t)NODES * HID];  // GEMM outputs
__device__ __align__(16) float g_x2 [(size_t)NODES * HID];  // aggregation outputs
__device__ __align__(16) float g_as [NODES];
__device__ __align__(16) float g_ad [NODES];
__device__ int g_cnt[NODES];
__device__ int g_rowptr[NODES + 1];
__device__ int g_fill[NODES];
__device__ int g_col[ETOT];
__device__ int g_tilesum[NTILES];
__device__ int g_tileoff[NTILES];
__device__ int g_is64;   // 1 if edge_index is int64 in memory, 0 if int32

// ---------------- cp.async helpers ----------------
__device__ __forceinline__ void cp_async16(uint32_t dst, const void* src, int src_bytes) {
    asm volatile("cp.async.cg.shared.global [%0], [%1], 16, %2;"
                 :: "r"(dst), "l"(src), "r"(src_bytes));
}
__device__ __forceinline__ void cp_commit() { asm volatile("cp.async.commit_group;"); }
template <int N>
__device__ __forceinline__ void cp_wait() { asm volatile("cp.async.wait_group %0;" :: "n"(N)); }

__device__ __forceinline__ uint32_t f2tf32(float x) {
    uint32_t r;
    asm("cvt.rna.tf32.f32 %0, %1;" : "=r"(r) : "f"(x));
    return r;
}
__device__ __forceinline__ void mma_tf32(float* d, const uint32_t* a, const uint32_t* b) {
    asm volatile(
        "mma.sync.aligned.m16n8k8.row.col.f32.tf32.tf32.f32 "
        "{%0,%1,%2,%3}, {%4,%5,%6,%7}, {%8,%9}, {%0,%1,%2,%3};"
        : "+f"(d[0]), "+f"(d[1]), "+f"(d[2]), "+f"(d[3])
        : "r"(a[0]), "r"(a[1]), "r"(a[2]), "r"(a[3]), "r"(b[0]), "r"(b[1]));
}

// ---------------- dtype probe: int64 layout => odd 32-bit words all zero ----
__global__ void probe_dtype_k(const unsigned int* __restrict__ ei32) {
    int lane = threadIdx.x;
    int odd_nonzero = 0;
    for (int i = lane; i < 64; i += 32)
        if (ei32[2 * i + 1] != 0u) odd_nonzero = 1;
    #pragma unroll
    for (int o = 16; o; o >>= 1)
        odd_nonzero |= __shfl_xor_sync(0xffffffffu, odd_nonzero, o);
    if (lane == 0) g_is64 = odd_nonzero ? 0 : 1;
}

__device__ __forceinline__ int load_edge(const void* ei, long long idx) {
    int v;
    if (g_is64) v = (int)((const long long*)ei)[idx];
    else        v = ((const int*)ei)[idx];
    return (v < 0) ? 0 : (v >= NODES ? NODES - 1 : v);
}

// ---------------- CSR build ----------------
__global__ void zero_cnt_k() {
    int i = blockIdx.x * blockDim.x + threadIdx.x;
    if (i < NODES) g_cnt[i] = 0;
}

__global__ void count_edges_k(const void* __restrict__ ei) {
    int e = blockIdx.x * blockDim.x + threadIdx.x;
    if (e >= ETOT) return;
    int dst = (e < NEDGE) ? load_edge(ei, (long long)NEDGE + e) : (e - NEDGE);
    atomicAdd(&g_cnt[dst], 1);
}

__global__ void scan_phase1_k() {
    __shared__ int sh[SCAN_BLK];
    int t = threadIdx.x;
    int i = blockIdx.x * SCAN_BLK + t;
    int v = (i < NODES) ? g_cnt[i] : 0;
    sh[t] = v;
    __syncthreads();
    for (int off = 1; off < SCAN_BLK; off <<= 1) {
        int x = 0;
        if (t >= off) x = sh[t - off];
        __syncthreads();
        sh[t] += x;
        __syncthreads();
    }
    if (i < NODES) g_rowptr[i] = sh[t] - v;
    if (t == SCAN_BLK - 1) g_tilesum[blockIdx.x] = sh[t];
}

__global__ void scan_phase2_k() {
    __shared__ int sh[64];
    int t = threadIdx.x;
    int v = (t < NTILES) ? g_tilesum[t] : 0;
    sh[t] = v;
    __syncthreads();
    for (int off = 1; off < 64; off <<= 1) {
        int x = 0;
        if (t >= off) x = sh[t - off];
        __syncthreads();
        sh[t] += x;
        __syncthreads();
    }
    if (t < NTILES) g_tileoff[t] = sh[t] - v;
    if (t == 63) g_rowptr[NODES] = sh[63];
}

__global__ void scan_phase3_k() {
    int i = blockIdx.x * blockDim.x + threadIdx.x;
    if (i >= NODES) return;
    int r = g_rowptr[i] + g_tileoff[i / SCAN_BLK];
    g_rowptr[i] = r;
    g_fill[i]   = r;
}

__global__ void fill_edges_k(const void* __restrict__ ei) {
    int e = blockIdx.x * blockDim.x + threadIdx.x;
    if (e >= ETOT) return;
    int src, dst;
    if (e < NEDGE) {
        src = load_edge(ei, e);
        dst = load_edge(ei, (long long)NEDGE + e);
    } else {
        src = dst = e - NEDGE;
    }
    int p = atomicAdd(&g_fill[dst], 1);
    g_col[p] = src;
}

// ---------------- TF32 tensor-core GEMM ----------------
// g_h[M x 128] = A[M x K] @ B[K x 128] (+bias)(relu); A_EXT: A from param, else g_x2.
// 256 thr = 8 warps (2m x 4n); warp tile 64x32 = 4x4 atoms of m16n8k8.
#define ASTR 20     // A smem row stride (floats): conflict-free frag loads
#define BSTR 136    // B smem row stride: (136*k) mod 32 = 8k -> conflict-free

template <bool A_EXT, bool BIAS, bool RELU>
__global__ __launch_bounds__(256, 2)
void gemm_tf32_k(const float* __restrict__ Ap, const float* __restrict__ B,
                 const float* __restrict__ bias, int M, int K) {
    const int BM = 128, BN = 128, BK = 16;
    const float* A = A_EXT ? Ap : (const float*)g_x2;
    float* C = g_h;

    __shared__ float As[2][BM][ASTR];
    __shared__ float Bs[2][BK][BSTR];

    const int tid  = threadIdx.x;
    const int lane = tid & 31;
    const int wid  = tid >> 5;
    const int wm   = (wid >> 2) * 64;      // 0 / 64
    const int wn   = (wid & 3) * 32;       // 0/32/64/96
    const int gid  = lane >> 2;            // 0..7
    const int tig  = lane & 3;             // 0..3
    const int block_row = blockIdx.x * BM;

    const int a_row  = tid / 4;      // 0..63 (two halves)
    const int a_col4 = tid % 4;
    const int b_row  = tid / 32;     // 0..7 (two halves)
    const int b_col4 = tid % 32;

    float acc[4][4][4];
    #pragma unroll
    for (int mt = 0; mt < 4; mt++)
        #pragma unroll
        for (int nt = 0; nt < 4; nt++)
            #pragma unroll
            for (int r = 0; r < 4; r++) acc[mt][nt][r] = 0.f;

    auto load_tile = [&](int k0, int s) {
        #pragma unroll
        for (int half = 0; half < 2; half++) {
            int r = a_row + half * 64;
            int grow = block_row + r;
            const float* src = A + (size_t)grow * K + k0 + a_col4 * 4;
            uint32_t dst = (uint32_t)__cvta_generic_to_shared(&As[s][r][a_col4 * 4]);
            cp_async16(dst, src, (grow < M) ? 16 : 0);
        }
        #pragma unroll
        for (int half = 0; half < 2; half++) {
            int r = b_row + half * 8;
            const float* src = B + (size_t)(k0 + r) * BN + b_col4 * 4;
            uint32_t dst = (uint32_t)__cvta_generic_to_shared(&Bs[s][r][b_col4 * 4]);
            cp_async16(dst, src, 16);
        }
    };

    load_tile(0, 0);
    cp_commit();

    int buf = 0;
    for (int k0 = 0; k0 < K; k0 += BK) {
        if (k0 + BK < K) load_tile(k0 + BK, buf ^ 1);
        cp_commit();
        cp_wait<1>();
        __syncthreads();

        #pragma unroll
        for (int ks = 0; ks < BK; ks += 8) {
            uint32_t afr[4][4];
            #pragma unroll
            for (int mt = 0; mt < 4; mt++) {
                int r = wm + mt * 16;
                afr[mt][0] = f2tf32(As[buf][r + gid     ][ks + tig    ]);
                afr[mt][1] = f2tf32(As[buf][r + gid + 8 ][ks + tig    ]);
                afr[mt][2] = f2tf32(As[buf][r + gid     ][ks + tig + 4]);
                afr[mt][3] = f2tf32(As[buf][r + gid + 8 ][ks + tig + 4]);
            }
            uint32_t bfr[4][2];
            #pragma unroll
            for (int nt = 0; nt < 4; nt++) {
                int c = wn + nt * 8 + gid;
                bfr[nt][0] = f2tf32(Bs[buf][ks + tig    ][c]);
                bfr[nt][1] = f2tf32(Bs[buf][ks + tig + 4][c]);
            }
            #pragma unroll
            for (int mt = 0; mt < 4; mt++)
                #pragma unroll
                for (int nt = 0; nt < 4; nt++)
                    mma_tf32(acc[mt][nt], afr[mt], bfr[nt]);
        }
        __syncthreads();
        buf ^= 1;
    }
    cp_wait<0>();

    // epilogue
    #pragma unroll
    for (int mt = 0; mt < 4; mt++) {
        #pragma unroll
        for (int nt = 0; nt < 4; nt++) {
            int col = wn + nt * 8 + 2 * tig;
            float b0 = 0.f, b1 = 0.f;
            if (BIAS) { b0 = bias[col]; b1 = bias[col + 1]; }
            #pragma unroll
            for (int half = 0; half < 2; half++) {
                int grow = block_row + wm + mt * 16 + gid + half * 8;
                if (grow >= M) continue;
                float v0 = acc[mt][nt][2 * half + 0] + b0;
                float v1 = acc[mt][nt][2 * half + 1] + b1;
                if (RELU) { v0 = fmaxf(v0, 0.f); v1 = fmaxf(v1, 0.f); }
                float2* dst = reinterpret_cast<float2*>(C + (size_t)grow * BN + col);
                *dst = make_float2(v0, v1);
            }
        }
    }
}

// ---------------- per-node attention dots on g_h -> g_as / g_ad ----------------
__global__ void node_dots_k(const float* __restrict__ a_src, const float* __restrict__ a_dst) {
    int node = blockIdx.x * (blockDim.x >> 5) + (threadIdx.x >> 5);
    if (node >= NODES) return;
    int lane = threadIdx.x & 31;
    float4 hv = reinterpret_cast<const float4*>(g_h + (size_t)node * HID)[lane];
    float4 s4 = reinterpret_cast<const float4*>(a_src)[lane];
    float4 d4 = reinterpret_cast<const float4*>(a_dst)[lane];
    float s = hv.x * s4.x + hv.y * s4.y + hv.z * s4.z + hv.w * s4.w;
    float d = hv.x * d4.x + hv.y * d4.y + hv.z * d4.z + hv.w * d4.w;
    #pragma unroll
    for (int o = 16; o; o >>= 1) {
        s += __shfl_xor_sync(0xffffffffu, s, o);
        d += __shfl_xor_sync(0xffffffffu, d, o);
    }
    if (lane == 0) { g_as[node] = s; g_ad[node] = d; }
}

// ---------------- GAT aggregation: one warp per destination node ----------------
template <bool RELU>
__global__ void gat_aggregate_k(const float* __restrict__ bias) {
    int node = blockIdx.x * (blockDim.x >> 5) + (threadIdx.x >> 5);
    if (node >= NODES) return;
    int lane = threadIdx.x & 31;
    int beg = g_rowptr[node], end = g_rowptr[node + 1];
    float adn = g_ad[node];

    float m = -INFINITY;
    for (int e = beg + lane; e < end; e += 32) {
        float l = g_as[g_col[e]] + adn;
        l = l > 0.f ? l : NEG_SLOPE * l;
        m = fmaxf(m, l);
    }
    #pragma unroll
    for (int o = 16; o; o >>= 1) m = fmaxf(m, __shfl_xor_sync(0xffffffffu, m, o));

    float4 acc = make_float4(0.f, 0.f, 0.f, 0.f);
    float denom = 0.f;
    for (int e = beg; e < end; e++) {
        int s = g_col[e];
        float l = g_as[s] + adn;
        l = l > 0.f ? l : NEG_SLOPE * l;
        float w = __expf(l - m);
        denom += w;
        float4 hv = reinterpret_cast<const float4*>(g_h + (size_t)s * HID)[lane];
        acc.x = fmaf(w, hv.x, acc.x);
        acc.y = fmaf(w, hv.y, acc.y);
        acc.z = fmaf(w, hv.z, acc.z);
        acc.w = fmaf(w, hv.w, acc.w);
    }
    float inv = 1.f / denom;
    float4 b4 = reinterpret_cast<const float4*>(bias)[lane];
    float4 o4;
    o4.x = acc.x * inv + b4.x;
    o4.y = acc.y * inv + b4.y;
    o4.z = acc.z * inv + b4.z;
    o4.w = acc.w * inv + b4.w;
    if (RELU) {
        o4.x = fmaxf(o4.x, 0.f); o4.y = fmaxf(o4.y, 0.f);
        o4.z = fmaxf(o4.z, 0.f); o4.w = fmaxf(o4.w, 0.f);
    }
    reinterpret_cast<float4*>(g_x2 + (size_t)node * HID)[lane] = o4;
}

// ---------------- final: out = sigmoid(g_h @ Wm2 + bm2), Wm2: [128 x 20] ----------------
__global__ void mlp_out_k(const float* __restrict__ W, const float* __restrict__ b,
                          float* __restrict__ out) {
    __shared__ float Ws[HID * NCLS];
    __shared__ float bs[NCLS];
    for (int i = threadIdx.x; i < HID * NCLS; i += blockDim.x) Ws[i] = W[i];
    if (threadIdx.x < NCLS) bs[threadIdx.x] = b[threadIdx.x];
    __syncthreads();
    int idx = blockIdx.x * blockDim.x + threadIdx.x;
    int row = idx / NCLS, c = idx % NCLS;
    if (row >= NODES) return;
    const float* zr = g_h + (size_t)row * HID;
    float acc = bs[c];
    #pragma unroll 8
    for (int k = 0; k < HID; k++) acc = fmaf(zr[k], Ws[k * NCLS + c], acc);
    out[idx] = 1.f / (1.f + __expf(-acc));
}

// ---------------- launch ----------------
extern "C" void kernel_launch(void* const* d_in, const int* in_sizes, int n_in,
                              void* d_out, int out_size) {
    const float* x    = (const float*)d_in[0];
    const void*  ei   = d_in[1];
    const float* W1   = (const float*)d_in[2];
    const float* as1  = (const float*)d_in[3];
    const float* ad1  = (const float*)d_in[4];
    const float* b1   = (const float*)d_in[5];
    const float* W2   = (const float*)d_in[6];
    const float* as2  = (const float*)d_in[7];
    const float* ad2  = (const float*)d_in[8];
    const float* b2   = (const float*)d_in[9];
    const float* Wm1  = (const float*)d_in[10];
    const float* bm1  = (const float*)d_in[11];
    const float* Wm2  = (const float*)d_in[12];
    const float* bm2  = (const float*)d_in[13];
    float*       out  = (float*)d_out;

    const int gemm_grid  = (NODES + 127) / 128;
    const int warps_grid = (NODES + 7) / 8;
    const int edge_grid  = (ETOT + 255) / 256;
    const int node_grid  = (NODES + 255) / 256;

    probe_dtype_k<<<1, 32>>>((const unsigned int*)ei);
    zero_cnt_k<<<node_grid, 256>>>();
    count_edges_k<<<edge_grid, 256>>>(ei);
    scan_phase1_k<<<NTILES, SCAN_BLK>>>();
    scan_phase2_k<<<1, 64>>>();
    scan_phase3_k<<<node_grid, 256>>>();
    fill_edges_k<<<edge_grid, 256>>>(ei);

    // --- GAT layer 1 ---
    gemm_tf32_k<true, false, false><<<gemm_grid, 256>>>(x, W1, nullptr, NODES, FIN);
    node_dots_k<<<warps_grid, 256>>>(as1, ad1);
    gat_aggregate_k<true><<<warps_grid, 256>>>(b1);

    // --- GAT layer 2 ---
    gemm_tf32_k<false, false, false><<<gemm_grid, 256>>>(nullptr, W2, nullptr, NODES, HID);
    node_dots_k<<<warps_grid, 256>>>(as2, ad2);
    gat_aggregate_k<false><<<warps_grid, 256>>>(b2);

    // --- MLP head ---
    gemm_tf32_k<false, true, true><<<gemm_grid, 256>>>(nullptr, Wm1, bm1, NODES, HID);
    mlp_out_k<<<(NODES * NCLS + 319) / 320, 320>>>(Wm2, bm2, out);
}